// round 7
// baseline (speedup 1.0000x reference)
#include <cuda_runtime.h>

#define BB 4
#define LL 256
#define DD 256

// scratch (allocation-free contract: __device__ globals)
__device__ float g_Sdep[BB * LL * DD];  // 1 MB : sum_j adj * dep
__device__ float g_S0[BB * LL * DD];    // 1 MB : adj @ text
__device__ float g_A[BB * LL];          // row sums of adj
__device__ float g_Wt[DD * DD];         // W transposed: Wt[d*256 + o]

// ---- packed f32x2 helpers (Blackwell FFMA2) --------------------------------
__device__ __forceinline__ unsigned long long splat2(float s) {
    unsigned long long r;
    asm("mov.b64 %0, {%1, %1};" : "=l"(r) : "f"(s));
    return r;
}
__device__ __forceinline__ void fma2(unsigned long long& acc,
                                     unsigned long long a,
                                     unsigned long long b) {
    asm("fma.rn.f32x2 %0, %1, %2, %0;" : "+l"(acc) : "l"(a), "l"(b));
}
__device__ __forceinline__ void unpk2(float& lo, float& hi, unsigned long long v) {
    asm("mov.b64 {%0, %1}, %2;" : "=f"(lo), "=f"(hi) : "l"(v));
}

// ---------------------------------------------------------------------------
// k_fused: grid = 1184 = 148 SMs x 8 CTAs  (exactly one resident wave)
//   bx in [0,128)    : S0[row,d] = sum_j adj[row,j]*text[b,j,d]; A[row]
//   bx in [128,160)  : W transpose -> g_Wt (2 tiles per block)
//   bx in [160,1184) : Sdep[b,i,d] = sum_j adj[b,i,j]*dep[b,j,i,d] (DRAM stream)
// ---------------------------------------------------------------------------
__global__ void __launch_bounds__(256) k_fused(const float* __restrict__ text,
                                               const float* __restrict__ adj,
                                               const float* __restrict__ dep,
                                               const float* __restrict__ W) {
    const int bx = blockIdx.x;
    const int t  = threadIdx.x;

    if (bx < 128) {
        // ---- S0 = adj @ text (8 rows per block), plus A row sums ----
        __shared__ float adjs[8][LL];
        const int row0 = bx * 8;            // global row = b*256 + i
        const int b    = row0 >> 8;

        const float* adjg = adj + (size_t)row0 * LL;
#pragma unroll
        for (int r = 0; r < 8; r++) adjs[r][t] = adjg[r * LL + t];
        __syncthreads();

        {   // A row sums: warp w reduces adjs[w]
            const int warp = t >> 5, lane = t & 31;
            float s = 0.f;
#pragma unroll
            for (int k = 0; k < 8; k++) s += adjs[warp][lane + 32 * k];
#pragma unroll
            for (int off = 16; off; off >>= 1)
                s += __shfl_xor_sync(0xffffffffu, s, off);
            if (lane == 0) g_A[row0 + warp] = s;
        }

        const int o4 = t & 63;
        const int rg = t >> 6;
        const int r0 = rg * 2, r1 = r0 + 1;

        const float4* text4 = (const float4*)text + ((size_t)b * LL << 6) + o4;
        float4 acc0 = make_float4(0.f, 0.f, 0.f, 0.f);
        float4 acc1 = make_float4(0.f, 0.f, 0.f, 0.f);

#pragma unroll 1
        for (int j = 0; j < LL; j += 4) {
            float4 tv[4];
#pragma unroll
            for (int u = 0; u < 4; u++) tv[u] = text4[(j + u) << 6];
#pragma unroll
            for (int u = 0; u < 4; u++) {
                const float a0 = adjs[r0][j + u];
                const float a1 = adjs[r1][j + u];
                acc0.x += a0 * tv[u].x;  acc0.y += a0 * tv[u].y;
                acc0.z += a0 * tv[u].z;  acc0.w += a0 * tv[u].w;
                acc1.x += a1 * tv[u].x;  acc1.y += a1 * tv[u].y;
                acc1.z += a1 * tv[u].z;  acc1.w += a1 * tv[u].w;
            }
        }
        ((float4*)g_S0)[((row0 + r0) << 6) + o4] = acc0;
        ((float4*)g_S0)[((row0 + r1) << 6) + o4] = acc1;
        return;
    }

    if (bx < 160) {
        // ---- W transpose: 32 blocks x 2 tiles of 32x32 ----
        __shared__ float tile[32][33];
        const int tx = t & 31, ty = t >> 5;   // (32, 8)
#pragma unroll 1
        for (int pass = 0; pass < 2; pass++) {
            const int bb = (bx - 128) + pass * 32;
            const int d0 = (bb & 7) * 32, o0 = (bb >> 3) * 32;
#pragma unroll
            for (int k = 0; k < 32; k += 8)
                tile[ty + k][tx] = W[(o0 + ty + k) * DD + (d0 + tx)];
            __syncthreads();
#pragma unroll
            for (int k = 0; k < 32; k += 8)
                g_Wt[(d0 + ty + k) * DD + (o0 + tx)] = tile[tx][ty + k];
            __syncthreads();
        }
        return;
    }

    // ---- dep stream: one (b,i) per block ----
    {
        const int id = bx - 160;
        const int b  = id >> 8;
        const int i  = id & 255;
        const int jj = t >> 6;
        const int d4 = t & 63;

        __shared__ float  adjs1[LL];
        __shared__ float4 red[4][64];

        adjs1[t] = adj[(b * LL + i) * LL + t];
        __syncthreads();

        const int jbase = jj << 6;
        const float4* p = (const float4*)dep
                        + (((size_t)(b * LL + jbase) * LL + i) << 6) + d4;
        const size_t jstride = (size_t)LL << 6;   // 16384 float4 per j

        float4 acc = make_float4(0.f, 0.f, 0.f, 0.f);

#pragma unroll 1
        for (int js = 0; js < 64; js += 8) {
            float4 dv[8];
#pragma unroll
            for (int u = 0; u < 8; u++)
                dv[u] = __ldcs(p + (size_t)u * jstride);   // 8 LDG.128 in flight
            p += jstride * 8;
#pragma unroll
            for (int u = 0; u < 8; u++) {
                const float a = adjs1[jbase + js + u];
                acc.x += a * dv[u].x;
                acc.y += a * dv[u].y;
                acc.z += a * dv[u].z;
                acc.w += a * dv[u].w;
            }
        }

        red[jj][d4] = acc;
        __syncthreads();
        if (t < 64) {
            float4 r0 = red[0][t], r1 = red[1][t], r2 = red[2][t], r3 = red[3][t];
            float4 s;
            s.x = (r0.x + r1.x) + (r2.x + r3.x);
            s.y = (r0.y + r1.y) + (r2.y + r3.y);
            s.z = (r0.z + r1.z) + (r2.z + r3.z);
            s.w = (r0.w + r1.w) + (r2.w + r3.w);
            ((float4*)g_Sdep)[((b * LL + i) << 6) + t] = s;
        }
    }
}

// ---------------------------------------------------------------------------
// k_out v7: out[row,o] = sum_d (S0+Sdep)[row,d]*Wt[d,o] + A[row]*bias[o]
// Tile 8 rows x 128 cols, grid 256, block 128 (4 warps). NO barriers in the
// main loop: each warp privately streams its 32-col Wt slice from L1/L2 with
// 8-deep LDG.128 batches; S is staged once in padded smem (conflict-free).
// FMA uses packed fma.rn.f32x2 (w float4 loaded directly as 2 packed pairs).
// Lane map: c = lane&7 (float4 col within warp slice), rq = lane>>3 -> rows
// rq*2, rq*2+1. All 256 blocks co-resident (~7 warps/SM).
// ---------------------------------------------------------------------------
__global__ void __launch_bounds__(128) k_out(const float* __restrict__ bias,
                                             float* __restrict__ out) {
    const int bx   = blockIdx.x;
    const int mt   = bx >> 1;
    const int nt   = bx & 1;
    const int row0 = mt * 8;
    const int t    = threadIdx.x;
    const int warp = t >> 5, lane = t & 31;
    const int c    = lane & 7;
    const int rq   = lane >> 3;
    const int col4 = nt * 32 + warp * 8 + c;   // global float4 col 0..63
    const int r0   = rq * 2, r1 = r0 + 1;

    __shared__ float Ssm[8][264];   // padded: row stride 264 floats
    __shared__ float Asm[8];

    // stage S = S0 + Sdep for the 8 rows (512 float4, 4 per thread)
    {
        const float4* S0g = (const float4*)(g_S0   + (size_t)row0 * DD);
        const float4* Sdg = (const float4*)(g_Sdep + (size_t)row0 * DD);
#pragma unroll
        for (int k = 0; k < 4; k++) {
            const int idx = t + 128 * k;
            const int rr = idx >> 6, cc = idx & 63;
            float4 a = S0g[idx];
            float4 b = Sdg[idx];
            a.x += b.x; a.y += b.y; a.z += b.z; a.w += b.w;
            *(float4*)&Ssm[rr][cc << 2] = a;
        }
        if (t < 8) Asm[t] = g_A[row0 + t];
    }
    __syncthreads();

    // Wt slice stream: Wt[d][col4*4 ..] as two packed f32x2
    const ulonglong2* Wtg = (const ulonglong2*)g_Wt + col4;

    unsigned long long a00 = 0ull, a01 = 0ull;   // row r0: cols (x,y), (z,w)
    unsigned long long a10 = 0ull, a11 = 0ull;   // row r1

#pragma unroll 1
    for (int d = 0; d < DD; d += 8) {
        ulonglong2 wv[8];
#pragma unroll
        for (int k = 0; k < 8; k++)
            wv[k] = Wtg[(d + k) << 6];          // 8 independent LDG.128

        const float4 s0a = *(const float4*)&Ssm[r0][d];
        const float4 s0b = *(const float4*)&Ssm[r0][d + 4];
        const float4 s1a = *(const float4*)&Ssm[r1][d];
        const float4 s1b = *(const float4*)&Ssm[r1][d + 4];
        const float s0[8] = {s0a.x, s0a.y, s0a.z, s0a.w, s0b.x, s0b.y, s0b.z, s0b.w};
        const float s1[8] = {s1a.x, s1a.y, s1a.z, s1a.w, s1b.x, s1b.y, s1b.z, s1b.w};

#pragma unroll
        for (int k = 0; k < 8; k++) {
            const unsigned long long sp0 = splat2(s0[k]);
            const unsigned long long sp1 = splat2(s1[k]);
            fma2(a00, wv[k].x, sp0);
            fma2(a01, wv[k].y, sp0);
            fma2(a10, wv[k].x, sp1);
            fma2(a11, wv[k].y, sp1);
        }
    }

    float o0x, o0y, o0z, o0w, o1x, o1y, o1z, o1w;
    unpk2(o0x, o0y, a00);  unpk2(o0z, o0w, a01);
    unpk2(o1x, o1y, a10);  unpk2(o1z, o1w, a11);

    const float4 bi = ((const float4*)bias)[col4];
    const float  b0 = Asm[r0];
    const float  b1 = Asm[r1];
    float4 res0, res1;
    res0.x = o0x + b0 * bi.x;  res0.y = o0y + b0 * bi.y;
    res0.z = o0z + b0 * bi.z;  res0.w = o0w + b0 * bi.w;
    res1.x = o1x + b1 * bi.x;  res1.y = o1y + b1 * bi.y;
    res1.z = o1z + b1 * bi.z;  res1.w = o1w + b1 * bi.w;

    ((float4*)(out + (size_t)(row0 + r0) * DD))[col4] = res0;
    ((float4*)(out + (size_t)(row0 + r1) * DD))[col4] = res1;
}

// ---------------------------------------------------------------------------
extern "C" void kernel_launch(void* const* d_in, const int* in_sizes, int n_in,
                              void* d_out, int out_size) {
    const float* text = (const float*)d_in[0];  // [4,256,256]
    const float* adj  = (const float*)d_in[1];  // [4,256,256]
    const float* dep  = (const float*)d_in[2];  // [4,256,256,256]
    const float* W    = (const float*)d_in[3];  // [256,256]
    const float* bias = (const float*)d_in[4];  // [256]
    float* out = (float*)d_out;                 // [4,256,256]

    k_fused<<<160 + BB * LL, 256>>>(text, adj, dep, W);   // 1184 = 148 x 8
    k_out<<<256, 128>>>(bias, out);
}

// round 8
// speedup vs baseline: 1.1955x; 1.1955x over previous
#include <cuda_runtime.h>

#define BB 4
#define LL 256
#define DD 256

// scratch (allocation-free contract: __device__ globals)
__device__ float g_Sdep[BB * LL * DD];  // 1 MB : sum_j adj * dep
__device__ float g_S0[BB * LL * DD];    // 1 MB : adj @ text
__device__ float g_A[BB * LL];          // row sums of adj
__device__ float g_Wt[DD * DD];         // W transposed: Wt[d*256 + o]

// ---- packed f32x2 helpers (Blackwell FFMA2) --------------------------------
__device__ __forceinline__ unsigned long long splat2(float s) {
    unsigned long long r;
    asm("mov.b64 %0, {%1, %1};" : "=l"(r) : "f"(s));
    return r;
}
__device__ __forceinline__ void fma2(unsigned long long& acc,
                                     unsigned long long a,
                                     unsigned long long b) {
    asm("fma.rn.f32x2 %0, %1, %2, %0;" : "+l"(acc) : "l"(a), "l"(b));
}
__device__ __forceinline__ void unpk2(float& lo, float& hi, unsigned long long v) {
    asm("mov.b64 {%0, %1}, %2;" : "=f"(lo), "=f"(hi) : "l"(v));
}

// ---------------------------------------------------------------------------
// k_fused: grid = 1184 = 148 SMs x 8 CTAs  (exactly one resident wave)
//   bx in [0,128)    : S0[row,d] = sum_j adj[row,j]*text[b,j,d]; A[row]
//   bx in [128,160)  : W transpose -> g_Wt (2 tiles per block)
//   bx in [160,1184) : Sdep[b,i,d] = sum_j adj[b,i,j]*dep[b,j,i,d] (DRAM stream)
// ---------------------------------------------------------------------------
__global__ void __launch_bounds__(256) k_fused(const float* __restrict__ text,
                                               const float* __restrict__ adj,
                                               const float* __restrict__ dep,
                                               const float* __restrict__ W) {
    const int bx = blockIdx.x;
    const int t  = threadIdx.x;

    if (bx < 128) {
        // ---- S0 = adj @ text (8 rows per block), plus A row sums ----
        __shared__ float adjs[8][LL];
        const int row0 = bx * 8;            // global row = b*256 + i
        const int b    = row0 >> 8;

        const float* adjg = adj + (size_t)row0 * LL;
#pragma unroll
        for (int r = 0; r < 8; r++) adjs[r][t] = adjg[r * LL + t];
        __syncthreads();

        {   // A row sums: warp w reduces adjs[w]
            const int warp = t >> 5, lane = t & 31;
            float s = 0.f;
#pragma unroll
            for (int k = 0; k < 8; k++) s += adjs[warp][lane + 32 * k];
#pragma unroll
            for (int off = 16; off; off >>= 1)
                s += __shfl_xor_sync(0xffffffffu, s, off);
            if (lane == 0) g_A[row0 + warp] = s;
        }

        const int o4 = t & 63;
        const int rg = t >> 6;
        const int r0 = rg * 2, r1 = r0 + 1;

        const float4* text4 = (const float4*)text + ((size_t)b * LL << 6) + o4;
        float4 acc0 = make_float4(0.f, 0.f, 0.f, 0.f);
        float4 acc1 = make_float4(0.f, 0.f, 0.f, 0.f);

#pragma unroll 1
        for (int j = 0; j < LL; j += 4) {
            float4 tv[4];
#pragma unroll
            for (int u = 0; u < 4; u++) tv[u] = text4[(j + u) << 6];
#pragma unroll
            for (int u = 0; u < 4; u++) {
                const float a0 = adjs[r0][j + u];
                const float a1 = adjs[r1][j + u];
                acc0.x += a0 * tv[u].x;  acc0.y += a0 * tv[u].y;
                acc0.z += a0 * tv[u].z;  acc0.w += a0 * tv[u].w;
                acc1.x += a1 * tv[u].x;  acc1.y += a1 * tv[u].y;
                acc1.z += a1 * tv[u].z;  acc1.w += a1 * tv[u].w;
            }
        }
        ((float4*)g_S0)[((row0 + r0) << 6) + o4] = acc0;
        ((float4*)g_S0)[((row0 + r1) << 6) + o4] = acc1;
        return;
    }

    if (bx < 160) {
        // ---- W transpose: 32 blocks x 2 tiles of 32x32 ----
        __shared__ float tile[32][33];
        const int tx = t & 31, ty = t >> 5;   // (32, 8)
#pragma unroll 1
        for (int pass = 0; pass < 2; pass++) {
            const int bb = (bx - 128) + pass * 32;
            const int d0 = (bb & 7) * 32, o0 = (bb >> 3) * 32;
#pragma unroll
            for (int k = 0; k < 32; k += 8)
                tile[ty + k][tx] = W[(o0 + ty + k) * DD + (d0 + tx)];
            __syncthreads();
#pragma unroll
            for (int k = 0; k < 32; k += 8)
                g_Wt[(d0 + ty + k) * DD + (o0 + tx)] = tile[tx][ty + k];
            __syncthreads();
        }
        return;
    }

    // ---- dep stream: one (b,i) per block ----
    {
        const int id = bx - 160;
        const int b  = id >> 8;
        const int i  = id & 255;
        const int jj = t >> 6;
        const int d4 = t & 63;

        __shared__ float  adjs1[LL];
        __shared__ float4 red[4][64];

        adjs1[t] = adj[(b * LL + i) * LL + t];
        __syncthreads();

        const int jbase = jj << 6;
        const float4* p = (const float4*)dep
                        + (((size_t)(b * LL + jbase) * LL + i) << 6) + d4;
        const size_t jstride = (size_t)LL << 6;   // 16384 float4 per j

        float4 acc = make_float4(0.f, 0.f, 0.f, 0.f);

#pragma unroll 1
        for (int js = 0; js < 64; js += 8) {
            float4 dv[8];
#pragma unroll
            for (int u = 0; u < 8; u++)
                dv[u] = __ldcs(p + (size_t)u * jstride);   // 8 LDG.128 in flight
            p += jstride * 8;
#pragma unroll
            for (int u = 0; u < 8; u++) {
                const float a = adjs1[jbase + js + u];
                acc.x += a * dv[u].x;
                acc.y += a * dv[u].y;
                acc.z += a * dv[u].z;
                acc.w += a * dv[u].w;
            }
        }

        red[jj][d4] = acc;
        __syncthreads();
        if (t < 64) {
            float4 r0 = red[0][t], r1 = red[1][t], r2 = red[2][t], r3 = red[3][t];
            float4 s;
            s.x = (r0.x + r1.x) + (r2.x + r3.x);
            s.y = (r0.y + r1.y) + (r2.y + r3.y);
            s.z = (r0.z + r1.z) + (r2.z + r3.z);
            s.w = (r0.w + r1.w) + (r2.w + r3.w);
            ((float4*)g_Sdep)[((b * LL + i) << 6) + t] = s;
        }
    }
}

// ---------------------------------------------------------------------------
// k_out v8: v6's proven double-buffered smem-Wt pipeline (regs stay high,
// MLP=8 on the global Wt stream) + packed fma.rn.f32x2 compute: w chunk read
// from smem as two packed f32x2 halves, one mov.b64 splat per (row,d), two
// FFMA2 per 4 scalar FMA -> ~384 instr/chunk vs 512, 8 independent acc chains.
// Tile: 16 rows x 128 cols, grid 128 blocks, block = 128 threads.
// ---------------------------------------------------------------------------
__global__ void __launch_bounds__(128) k_out(const float* __restrict__ bias,
                                             float* __restrict__ out) {
    const int bx   = blockIdx.x;
    const int mt   = bx >> 1;
    const int nt   = bx & 1;
    const int row0 = mt * 16;
    const int t    = threadIdx.x;
    const int c4   = t & 31;      // float4 col within the 128-col half
    const int rg   = t >> 5;      // row group 0..3 -> rows rg*4 .. rg*4+3

    __shared__ float  Ssm[16][DD];      // 16 KB
    __shared__ float  Asm[16];
    __shared__ float4 Wts[2][32][32];   // 2 x 16 KB double buffer

    // stage S = S0 + Sdep for the 16 rows (1024 float4, 8 per thread)
    {
        const float4* S0g = (const float4*)(g_S0   + (size_t)row0 * DD);
        const float4* Sdg = (const float4*)(g_Sdep + (size_t)row0 * DD);
        float4* Ss4 = (float4*)&Ssm[0][0];
#pragma unroll
        for (int k = 0; k < 8; k++) {
            const int idx = t + 128 * k;
            float4 a = S0g[idx];
            float4 c = Sdg[idx];
            a.x += c.x; a.y += c.y; a.z += c.z; a.w += c.w;
            Ss4[idx] = a;
        }
        if (t < 16) Asm[t] = g_A[row0 + t];
    }

    // Wt global pointer for this block's column half; per chunk this thread
    // loads 8 d's: d = dbase + rg*8 + k  -> 8 independent LDG.128 (MLP=8)
    const float4* Wtg = (const float4*)g_Wt + nt * 32 + c4;

    float4 pre[8];
#pragma unroll
    for (int k = 0; k < 8; k++)
        pre[k] = Wtg[(rg * 8 + k) << 6];

    // packed accumulators: row j -> (cols x,y) in accL[j], (cols z,w) in accH[j]
    unsigned long long accL[4], accH[4];
#pragma unroll
    for (int j = 0; j < 4; j++) { accL[j] = 0ull; accH[j] = 0ull; }
    const int rbase = rg * 4;

#pragma unroll 1
    for (int ch = 0; ch < 8; ch++) {
        const int buf = ch & 1;
        // commit prefetched chunk to smem (conflict-free: row fixed, c4 0..31)
#pragma unroll
        for (int k = 0; k < 8; k++)
            Wts[buf][rg * 8 + k][c4] = pre[k];
        __syncthreads();

        // issue next chunk's loads (overlap with compute below)
        if (ch < 7) {
            const int dbase = (ch + 1) * 32;
#pragma unroll
            for (int k = 0; k < 8; k++)
                pre[k] = Wtg[(dbase + rg * 8 + k) << 6];
        }

        // compute this chunk: 4 rows x 4 cols x 32 d, packed f32x2
        const int dc = ch * 32;
#pragma unroll
        for (int dq = 0; dq < 8; dq++) {
            const ulonglong2 w0 = *(const ulonglong2*)&Wts[buf][dq * 4 + 0][c4];
            const ulonglong2 w1 = *(const ulonglong2*)&Wts[buf][dq * 4 + 1][c4];
            const ulonglong2 w2 = *(const ulonglong2*)&Wts[buf][dq * 4 + 2][c4];
            const ulonglong2 w3 = *(const ulonglong2*)&Wts[buf][dq * 4 + 3][c4];
#pragma unroll
            for (int j = 0; j < 4; j++) {
                const float4 s = *(const float4*)&Ssm[rbase + j][dc + dq * 4]; // bcast
                unsigned long long sp;
                sp = splat2(s.x);
                fma2(accL[j], w0.x, sp);  fma2(accH[j], w0.y, sp);
                sp = splat2(s.y);
                fma2(accL[j], w1.x, sp);  fma2(accH[j], w1.y, sp);
                sp = splat2(s.z);
                fma2(accL[j], w2.x, sp);  fma2(accH[j], w2.y, sp);
                sp = splat2(s.w);
                fma2(accL[j], w3.x, sp);  fma2(accH[j], w3.y, sp);
            }
        }
        __syncthreads();
    }

    const float4 bi = ((const float4*)bias)[nt * 32 + c4];
#pragma unroll
    for (int j = 0; j < 4; j++) {
        float4 r;
        unpk2(r.x, r.y, accL[j]);
        unpk2(r.z, r.w, accH[j]);
        const float a = Asm[rbase + j];
        r.x += a * bi.x;  r.y += a * bi.y;
        r.z += a * bi.z;  r.w += a * bi.w;
        ((float4*)(out + (size_t)(row0 + rbase + j) * DD))[nt * 32 + c4] = r;
    }
}

// ---------------------------------------------------------------------------
extern "C" void kernel_launch(void* const* d_in, const int* in_sizes, int n_in,
                              void* d_out, int out_size) {
    const float* text = (const float*)d_in[0];  // [4,256,256]
    const float* adj  = (const float*)d_in[1];  // [4,256,256]
    const float* dep  = (const float*)d_in[2];  // [4,256,256,256]
    const float* W    = (const float*)d_in[3];  // [256,256]
    const float* bias = (const float*)d_in[4];  // [256]
    float* out = (float*)d_out;                 // [4,256,256]

    k_fused<<<160 + BB * LL, 256>>>(text, adj, dep, W);   // 1184 = 148 x 8
    k_out<<<128, 128>>>(bias, out);
}

// round 9
// speedup vs baseline: 1.2363x; 1.0341x over previous
#include <cuda_runtime.h>

#define BB 4
#define LL 256
#define DD 256

// scratch (allocation-free contract: __device__ globals, zero-initialized)
__device__ float g_Sdep[BB * LL * DD];  // 1 MB : sum_j adj * dep
__device__ float g_S0[BB * LL * DD];    // 1 MB : adj @ text
__device__ float g_A[BB * LL];          // row sums of adj
__device__ float g_Wt[DD * DD];         // W transposed: Wt[d*256 + o]

// dataflow sync state (must be 0 at every launch; last out block resets)
__device__ volatile int g_depflag[BB * LL];  // per-row "Sdep row ready"
__device__ int g_wtcnt;                      // transpose blocks done (32)
__device__ int g_outcnt;                     // out blocks done (128)

// ---------------------------------------------------------------------------
// k_mega: ONE kernel, grid 1184 x 256.
//   bx in [0,128)    : S0[8 rows] + A  ->  then WAIT (Wt, own 8 dep rows)
//                      -> out tile: out[8 rows, 256 cols]
//   bx in [128,160)  : W transpose -> g_Wt, then g_wtcnt++
//   bx in [160,1184) : Sdep row (b,i) = sum_j adj[b,i,j]*dep[b,j,i,:]
//                      then g_depflag[row] = 1
// __launch_bounds__(256,3): >=3 blocks/SM resident -> waiters (128 blocks)
// can never starve dep producers; dep BW holds (in-flight >> BW*latency).
// ---------------------------------------------------------------------------
__global__ void __launch_bounds__(256, 3)
k_mega(const float* __restrict__ text,
       const float* __restrict__ adj,
       const float* __restrict__ dep,
       const float* __restrict__ W,
       const float* __restrict__ bias,
       float* __restrict__ out) {
    const int bx = blockIdx.x;
    const int t  = threadIdx.x;

    // shared buffer union across roles (max user: out stage 8484 B)
    __shared__ __align__(16) char smraw[8704];

    // =========================== transpose role ===========================
    if (bx >= 128 && bx < 160) {
        float (*tile)[33] = (float (*)[33])smraw;
        const int tx = t & 31, ty = t >> 5;   // (32, 8)
#pragma unroll 1
        for (int pass = 0; pass < 2; pass++) {
            const int bb = (bx - 128) + pass * 32;
            const int d0 = (bb & 7) * 32, o0 = (bb >> 3) * 32;
#pragma unroll
            for (int k = 0; k < 32; k += 8)
                tile[ty + k][tx] = W[(o0 + ty + k) * DD + (d0 + tx)];
            __syncthreads();
#pragma unroll
            for (int k = 0; k < 32; k += 8)
                g_Wt[(d0 + ty + k) * DD + (o0 + tx)] = tile[tx][ty + k];
            __syncthreads();
        }
        __threadfence();
        __syncthreads();
        if (t == 0) atomicAdd(&g_wtcnt, 1);
        return;
    }

    // ============================= dep role ===============================
    if (bx >= 160) {
        const int id = bx - 160;          // global row = b*256 + i
        const int b  = id >> 8;
        const int i  = id & 255;
        const int jj = t >> 6;
        const int d4 = t & 63;

        float*  adjs1 = (float*)smraw;                  // [256]
        float4* red   = (float4*)(smraw + 1024);        // [4][64]

        adjs1[t] = adj[(b * LL + i) * LL + t];
        __syncthreads();

        const int jbase = jj << 6;
        const float4* p = (const float4*)dep
                        + (((size_t)(b * LL + jbase) * LL + i) << 6) + d4;
        const size_t jstride = (size_t)LL << 6;   // 16384 float4 per j

        float4 acc = make_float4(0.f, 0.f, 0.f, 0.f);

#pragma unroll 1
        for (int js = 0; js < 64; js += 8) {
            float4 dv[8];
#pragma unroll
            for (int u = 0; u < 8; u++)
                dv[u] = __ldcs(p + (size_t)u * jstride);   // 8 LDG.128 in flight
            p += jstride * 8;
#pragma unroll
            for (int u = 0; u < 8; u++) {
                const float a = adjs1[jbase + js + u];
                acc.x += a * dv[u].x;
                acc.y += a * dv[u].y;
                acc.z += a * dv[u].z;
                acc.w += a * dv[u].w;
            }
        }

        red[(jj << 6) + d4] = acc;
        __syncthreads();
        if (t < 64) {
            float4 r0 = red[t], r1 = red[64 + t], r2 = red[128 + t], r3 = red[192 + t];
            float4 s;
            s.x = (r0.x + r1.x) + (r2.x + r3.x);
            s.y = (r0.y + r1.y) + (r2.y + r3.y);
            s.z = (r0.z + r1.z) + (r2.z + r3.z);
            s.w = (r0.w + r1.w) + (r2.w + r3.w);
            ((float4*)g_Sdep)[(id << 6) + t] = s;
        }
        __threadfence();      // make Sdep row gpu-visible (all writers fenced)
        __syncthreads();
        if (t == 0) g_depflag[id] = 1;    // volatile release-ish publish
        return;
    }

    // ======================= gemm (+ out) role: bx < 128 ===================
    const int row0 = bx * 8;              // global rows row0..row0+7
    const int b    = row0 >> 8;

    {   // ---- S0 = adj @ text (8 rows), plus A row sums ----
        float (*adjs)[LL] = (float (*)[LL])smraw;
        const float* adjg = adj + (size_t)row0 * LL;
#pragma unroll
        for (int r = 0; r < 8; r++) adjs[r][t] = adjg[r * LL + t];
        __syncthreads();

        {   // A row sums: warp w reduces adjs[w]
            const int warp = t >> 5, lane = t & 31;
            float s = 0.f;
#pragma unroll
            for (int k = 0; k < 8; k++) s += adjs[warp][lane + 32 * k];
#pragma unroll
            for (int off = 16; off; off >>= 1)
                s += __shfl_xor_sync(0xffffffffu, s, off);
            if (lane == 0) g_A[row0 + warp] = s;
        }

        const int o4 = t & 63;
        const int rg = t >> 6;
        const int r0 = rg * 2, r1 = r0 + 1;

        const float4* text4 = (const float4*)text + ((size_t)b * LL << 6) + o4;
        float4 acc0 = make_float4(0.f, 0.f, 0.f, 0.f);
        float4 acc1 = make_float4(0.f, 0.f, 0.f, 0.f);

#pragma unroll 1
        for (int j = 0; j < LL; j += 4) {
            float4 tv[4];
#pragma unroll
            for (int u = 0; u < 4; u++) tv[u] = text4[(j + u) << 6];
#pragma unroll
            for (int u = 0; u < 4; u++) {
                const float a0 = adjs[r0][j + u];
                const float a1 = adjs[r1][j + u];
                acc0.x += a0 * tv[u].x;  acc0.y += a0 * tv[u].y;
                acc0.z += a0 * tv[u].z;  acc0.w += a0 * tv[u].w;
                acc1.x += a1 * tv[u].x;  acc1.y += a1 * tv[u].y;
                acc1.z += a1 * tv[u].z;  acc1.w += a1 * tv[u].w;
            }
        }
        ((float4*)g_S0)[((row0 + r0) << 6) + o4] = acc0;
        ((float4*)g_S0)[((row0 + r1) << 6) + o4] = acc1;
    }
    __syncthreads();   // done with adjs smem; safe to reuse

    // ---- wait for Wt (32 transpose blocks) and our 8 Sdep rows ----
    if (t == 0) {
        while (atomicAdd(&g_wtcnt, 0) < 32) __nanosleep(256);
#pragma unroll 1
        for (int r = 0; r < 8; r++)
            while (g_depflag[row0 + r] == 0) __nanosleep(256);
    }
    __syncthreads();
    __threadfence();   // acquire: order subsequent reads after flag observation

    // ---- stage S = S0 + Sdep (8 rows, padded stride 264) + A ----
    float* Ss = (float*)smraw;                       // [8][264]
    float* Aa = (float*)(smraw + 8448);              // [8]
    int*   lastf = (int*)(smraw + 8480);
    {
        const float4* S0g = (const float4*)(g_S0   + (size_t)row0 * DD);
        const float4* Sdg = (const float4*)(g_Sdep + (size_t)row0 * DD);
#pragma unroll
        for (int k = 0; k < 2; k++) {
            const int idx = t + 256 * k;
            const int rr = idx >> 6, cc = idx & 63;
            float4 a = S0g[idx];
            float4 c = Sdg[idx];
            a.x += c.x; a.y += c.y; a.z += c.z; a.w += c.w;
            *(float4*)&Ss[rr * 264 + (cc << 2)] = a;
        }
        if (t < 8) Aa[t] = g_A[row0 + t];
    }
    __syncthreads();

    // ---- out compute: 8 rows x 256 cols, barrier-free Wt stream ----
    // warp w: float4 cols w*8 + (lane&7); rq = lane>>3 -> rows 2rq, 2rq+1
    {
        const int lane = t & 31;
        const int col4 = (t >> 5) * 8 + (lane & 7);
        const int rq   = lane >> 3;
        const int r0   = rq * 2, r1 = r0 + 1;

        const float4* Wtg = (const float4*)g_Wt + col4;
        float4 acc0 = make_float4(0.f, 0.f, 0.f, 0.f);
        float4 acc1 = make_float4(0.f, 0.f, 0.f, 0.f);

#pragma unroll 1
        for (int d = 0; d < DD; d += 8) {
            float4 wv[8];
#pragma unroll
            for (int k = 0; k < 8; k++)
                wv[k] = Wtg[(d + k) << 6];          // 8 independent LDG.128

            const float4 s0a = *(const float4*)&Ss[r0 * 264 + d];
            const float4 s0b = *(const float4*)&Ss[r0 * 264 + d + 4];
            const float4 s1a = *(const float4*)&Ss[r1 * 264 + d];
            const float4 s1b = *(const float4*)&Ss[r1 * 264 + d + 4];
            const float s0[8] = {s0a.x, s0a.y, s0a.z, s0a.w, s0b.x, s0b.y, s0b.z, s0b.w};
            const float s1[8] = {s1a.x, s1a.y, s1a.z, s1a.w, s1b.x, s1b.y, s1b.z, s1b.w};

#pragma unroll
            for (int k = 0; k < 8; k++) {
                acc0.x += s0[k] * wv[k].x;  acc0.y += s0[k] * wv[k].y;
                acc0.z += s0[k] * wv[k].z;  acc0.w += s0[k] * wv[k].w;
                acc1.x += s1[k] * wv[k].x;  acc1.y += s1[k] * wv[k].y;
                acc1.z += s1[k] * wv[k].z;  acc1.w += s1[k] * wv[k].w;
            }
        }

        const float4 bi = ((const float4*)bias)[col4];
        const float  a0 = Aa[r0];
        const float  a1 = Aa[r1];
        acc0.x += a0 * bi.x;  acc0.y += a0 * bi.y;
        acc0.z += a0 * bi.z;  acc0.w += a0 * bi.w;
        acc1.x += a1 * bi.x;  acc1.y += a1 * bi.y;
        acc1.z += a1 * bi.z;  acc1.w += a1 * bi.w;

        ((float4*)(out + (size_t)(row0 + r0) * DD))[col4] = acc0;
        ((float4*)(out + (size_t)(row0 + r1) * DD))[col4] = acc1;
    }

    // ---- last out block resets all sync state for the next graph replay ----
    __syncthreads();
    if (t == 0) *lastf = (atomicAdd(&g_outcnt, 1) == 127) ? 1 : 0;
    __syncthreads();
    if (*lastf) {
        for (int i = t; i < BB * LL; i += 256) g_depflag[i] = 0;
        if (t == 0) { g_wtcnt = 0; g_outcnt = 0; }
    }
}

// ---------------------------------------------------------------------------
extern "C" void kernel_launch(void* const* d_in, const int* in_sizes, int n_in,
                              void* d_out, int out_size) {
    const float* text = (const float*)d_in[0];  // [4,256,256]
    const float* adj  = (const float*)d_in[1];  // [4,256,256]
    const float* dep  = (const float*)d_in[2];  // [4,256,256,256]
    const float* W    = (const float*)d_in[3];  // [256,256]
    const float* bias = (const float*)d_in[4];  // [256]
    float* out = (float*)d_out;                 // [4,256,256]

    k_mega<<<160 + BB * LL, 256>>>(text, adj, dep, W, bias, out);
}